// round 1
// baseline (speedup 1.0000x reference)
#include <cuda_runtime.h>
#include <math.h>

// ---------------- problem constants ----------------
#define L_SEQ 2048
#define DM    1024
#define DI    2048
#define NS    16
#define KC    4
#define NPROJ (DI + 2*NS)   // 2080

// ---------------- scratch (device globals; no cudaMalloc allowed) ----------------
__device__ float g_xr  [L_SEQ * 2 * DI];   // 2048 x 4096 : [xi_pre | res]
__device__ float g_xi  [L_SEQ * DI];       // 2048 x 2048 : silu(conv(xi_pre))
__device__ float g_proj[L_SEQ * NPROJ];    // 2048 x 2080 : [softplus(delta) | B | C]
__device__ float g_z   [L_SEQ * DI];       // 2048 x 2048 : scan output (pre out-proj)

__device__ __forceinline__ float softplus_f(float x) {
    return fmaxf(x, 0.f) + log1pf(expf(-fabsf(x)));
}

// ============================================================================
// SGEMM:  C[M,Nc] = A[M,K] * W[Nc,K]^T + bias   (both K-contiguous row-major)
// ACT==1: apply softplus to columns < DI (delta part of proj)
// 128x128 block tile, BK=8, 8x8 microtile, 256 threads.
// ============================================================================
template<int ACT>
__global__ __launch_bounds__(256, 2)
void sgemm_nt(const float* __restrict__ A, const float* __restrict__ W,
              const float* __restrict__ bias, float* __restrict__ C,
              int M, int Nc, int Kd)
{
    const int BM = 128, BN = 128, BK = 8, TM = 8, TN = 8;
    __shared__ float As[BK][BM + 4];
    __shared__ float Ws[BK][BN + 4];

    int tid = threadIdx.x;
    int tx = tid & 15;          // 0..15 -> N direction
    int ty = tid >> 4;          // 0..15 -> M direction
    int rowBase = blockIdx.y * BM;
    int colBase = blockIdx.x * BN;

    // cooperative load mapping: 256 threads, each loads one float4 of A and W
    int ldRow = tid >> 1;          // 0..127
    int ldCol = (tid & 1) * 4;     // 0 or 4

    const float* Ap = A + (size_t)(rowBase + ldRow) * Kd + ldCol;
    bool wValid = (colBase + ldRow) < Nc;
    const float* Wp = W + (size_t)(colBase + ldRow) * Kd + ldCol;

    float acc[TM][TN];
#pragma unroll
    for (int i = 0; i < TM; i++)
#pragma unroll
        for (int j = 0; j < TN; j++) acc[i][j] = 0.f;

    float4 av = *(const float4*)Ap;
    float4 wv = wValid ? *(const float4*)Wp : make_float4(0.f, 0.f, 0.f, 0.f);

    for (int k0 = 0; k0 < Kd; k0 += BK) {
        __syncthreads();
        As[ldCol + 0][ldRow] = av.x;
        As[ldCol + 1][ldRow] = av.y;
        As[ldCol + 2][ldRow] = av.z;
        As[ldCol + 3][ldRow] = av.w;
        Ws[ldCol + 0][ldRow] = wv.x;
        Ws[ldCol + 1][ldRow] = wv.y;
        Ws[ldCol + 2][ldRow] = wv.z;
        Ws[ldCol + 3][ldRow] = wv.w;
        __syncthreads();

        if (k0 + BK < Kd) {  // prefetch next K-slab into registers (hides LDG)
            av = *(const float4*)(Ap + k0 + BK);
            wv = wValid ? *(const float4*)(Wp + k0 + BK) : make_float4(0.f, 0.f, 0.f, 0.f);
        }

#pragma unroll
        for (int k = 0; k < BK; k++) {
            float ra[TM], rb[TN];
            *(float4*)&ra[0] = *(const float4*)&As[k][ty * TM];
            *(float4*)&ra[4] = *(const float4*)&As[k][ty * TM + 4];
            *(float4*)&rb[0] = *(const float4*)&Ws[k][tx * TN];
            *(float4*)&rb[4] = *(const float4*)&Ws[k][tx * TN + 4];
#pragma unroll
            for (int i = 0; i < TM; i++)
#pragma unroll
                for (int j = 0; j < TN; j++)
                    acc[i][j] = fmaf(ra[i], rb[j], acc[i][j]);
        }
    }

#pragma unroll
    for (int i = 0; i < TM; i++) {
        int r = rowBase + ty * TM + i;
#pragma unroll
        for (int j = 0; j < TN; j++) {
            int c = colBase + tx * TN + j;
            if (c < Nc) {
                float v = acc[i][j] + bias[c];
                if (ACT == 1 && c < DI) v = softplus_f(v);
                C[(size_t)r * Nc + c] = v;
            }
        }
    }
}

// ============================================================================
// Depthwise causal conv (K=4) + silu:  xi[t,d] = silu(b[d] + sum_k w[d,k]*xr[t-3+k, d])
// ============================================================================
__global__ __launch_bounds__(256)
void conv_silu_k(const float* __restrict__ Wc, const float* __restrict__ bc)
{
    int idx = blockIdx.x * blockDim.x + threadIdx.x;  // over L*DI
    int t = idx >> 11;       // / 2048
    int d = idx & (DI - 1);

    float acc = bc[d];
#pragma unroll
    for (int k = 0; k < KC; k++) {
        int tt = t - (KC - 1) + k;
        if (tt >= 0)
            acc = fmaf(Wc[d * KC + k], g_xr[(size_t)tt * (2 * DI) + d], acc);
    }
    float s = acc / (1.f + __expf(-acc));   // silu
    g_xi[(size_t)t * DI + d] = s;
}

// ============================================================================
// Fused selective scan + gating.
// Block: 16 d-channels x 16 states = 256 threads; grid = DI/16 = 128 blocks.
// Double-buffered cp.async time tiles of TT=32 steps.
// ============================================================================
__device__ __forceinline__ void cp_async16(void* sm, const void* gm) {
    unsigned s = (unsigned)__cvta_generic_to_shared(sm);
    asm volatile("cp.async.ca.shared.global [%0], [%1], 16;" :: "r"(s), "l"(gm));
}
__device__ __forceinline__ void cp_commit() { asm volatile("cp.async.commit_group;"); }
template<int N> __device__ __forceinline__ void cp_wait() {
    asm volatile("cp.async.wait_group %0;" :: "n"(N));
}

#define TT 32

__global__ __launch_bounds__(256, 1)
void scan_k(const float* __restrict__ A_log, const float* __restrict__ Dv)
{
    __shared__ float s_delta[2][TT][16];
    __shared__ float s_B    [2][TT][16];
    __shared__ float s_C    [2][TT][16];
    __shared__ float s_xi   [2][TT][16];
    __shared__ float s_res  [2][TT][16];

    int tid = threadIdx.x;
    int n  = tid & 15;   // state index
    int dl = tid >> 4;   // local channel
    int dbase = blockIdx.x * 16;
    int d = dbase + dl;

    float A_dn = -expf(A_log[d * NS + n]);
    float Dd   = Dv[d];
    float h    = 0.f;

    auto issue = [&](int t0, int buf) {
        // 5 arrays x 32 steps x 4 float4 = 640 cp.async tasks
        for (int q = tid; q < 5 * TT * 4; q += 256) {
            int arr = q >> 7;
            int rem = q & 127;
            int tq  = rem >> 2;
            int v   = (rem & 3) * 4;
            int t   = t0 + tq;
            const float* g; float* s;
            if      (arr == 0) { g = g_proj + (size_t)t * NPROJ + dbase + v;      s = &s_delta[buf][tq][v]; }
            else if (arr == 1) { g = g_proj + (size_t)t * NPROJ + DI + v;         s = &s_B[buf][tq][v]; }
            else if (arr == 2) { g = g_proj + (size_t)t * NPROJ + DI + NS + v;    s = &s_C[buf][tq][v]; }
            else if (arr == 3) { g = g_xi   + (size_t)t * DI + dbase + v;         s = &s_xi[buf][tq][v]; }
            else               { g = g_xr   + (size_t)t * (2*DI) + DI + dbase + v; s = &s_res[buf][tq][v]; }
            cp_async16(s, g);
        }
        cp_commit();
    };

    issue(0, 0);
    int buf = 0;
    const int NT = L_SEQ / TT;  // 64 tiles
    for (int it = 0; it < NT; it++) {
        if (it + 1 < NT) { issue((it + 1) * TT, buf ^ 1); cp_wait<1>(); }
        else             { cp_wait<0>(); }
        __syncthreads();

        int t0 = it * TT;
#pragma unroll 8
        for (int tt = 0; tt < TT; tt++) {
            float del = s_delta[buf][tt][dl];
            float bv  = s_B[buf][tt][n];
            float cv  = s_C[buf][tt][n];
            float xv  = s_xi[buf][tt][dl];
            float dA  = __expf(del * A_dn);
            h = fmaf(dA, h, del * bv * xv);
            float yv = h * cv;
            // reduce over 16 state lanes (stays within each 16-lane half)
            yv += __shfl_xor_sync(0xffffffffu, yv, 1);
            yv += __shfl_xor_sync(0xffffffffu, yv, 2);
            yv += __shfl_xor_sync(0xffffffffu, yv, 4);
            yv += __shfl_xor_sync(0xffffffffu, yv, 8);
            if (n == 0) {
                float r  = s_res[buf][tt][dl];
                float y  = fmaf(xv, Dd, yv);
                float zv = y * (r / (1.f + __expf(-r)));   // y * silu(res)
                g_z[(size_t)(t0 + tt) * DI + d] = zv;
            }
        }
        __syncthreads();
        buf ^= 1;
    }
}

// ============================================================================
// launch
// ============================================================================
extern "C" void kernel_launch(void* const* d_in, const int* in_sizes, int n_in,
                              void* d_out, int out_size)
{
    const float* x      = (const float*)d_in[0];
    const float* W_in   = (const float*)d_in[1];
    const float* b_in   = (const float*)d_in[2];
    const float* W_conv = (const float*)d_in[3];
    const float* b_conv = (const float*)d_in[4];
    const float* W_x    = (const float*)d_in[5];
    const float* b_x    = (const float*)d_in[6];
    const float* W_out  = (const float*)d_in[7];
    const float* b_out  = (const float*)d_in[8];
    const float* A_log  = (const float*)d_in[9];
    const float* Dv     = (const float*)d_in[10];
    float* out = (float*)d_out;

    float *xr, *xi, *proj, *z;
    cudaGetSymbolAddress((void**)&xr,   g_xr);
    cudaGetSymbolAddress((void**)&xi,   g_xi);
    cudaGetSymbolAddress((void**)&proj, g_proj);
    cudaGetSymbolAddress((void**)&z,    g_z);

    // 1) xr = x @ W_in.T + b_in                          (2048x1024x4096)
    {
        dim3 grid((2 * 2 * DI) / 128, L_SEQ / 128);       // (32,16)
        sgemm_nt<0><<<grid, 256>>>(x, W_in, b_in, xr, L_SEQ, 2 * DI, DM);
    }
    // 2) xi = silu(causal_conv(xr[:, :DI]))
    {
        conv_silu_k<<<(L_SEQ * DI) / 256, 256>>>(W_conv, b_conv);
    }
    // 3) proj = xi @ W_x.T + b_x ; softplus on delta cols (2048x2048x2080)
    {
        dim3 grid((NPROJ + 127) / 128, L_SEQ / 128);      // (17,16)
        sgemm_nt<1><<<grid, 256>>>(xi, W_x, b_x, proj, L_SEQ, NPROJ, DI);
    }
    // 4) fused selective scan + gating -> z
    {
        scan_k<<<DI / 16, 256>>>(A_log, Dv);
    }
    // 5) out = z @ W_out.T + b_out                       (2048x2048x1024)
    {
        dim3 grid(DM / 128, L_SEQ / 128);                 // (8,16)
        sgemm_nt<0><<<grid, 256>>>(z, W_out, b_out, out, L_SEQ, DM, DI);
    }
}

// round 3
// speedup vs baseline: 3.0826x; 3.0826x over previous
#include <cuda_runtime.h>
#include <cuda_bf16.h>
#include <math.h>
#include <stdint.h>

// ---------------- problem constants ----------------
#define L_SEQ 2048
#define DM    1024
#define DI    2048
#define NST   16
#define KC    4
#define NPROJ (DI + 2*NST)   // 2080

#define NCH   16             // scan chunks
#define CH    128            // steps per chunk

// ---------------- scratch (device globals) ----------------
__device__ float g_xr  [L_SEQ * 2 * DI];
__device__ float g_xi  [L_SEQ * DI];
__device__ float g_proj[L_SEQ * NPROJ];
__device__ float g_z   [L_SEQ * DI];

__device__ __nv_bfloat16 g_ahi[L_SEQ * DI];
__device__ __nv_bfloat16 g_alo[L_SEQ * DI];
__device__ __nv_bfloat16 g_whi[NPROJ * DI];
__device__ __nv_bfloat16 g_wlo[NPROJ * DI];

__device__ float g_cA[NCH * DI * NST];   // per-chunk prod(dA)
__device__ float g_cB[NCH * DI * NST];   // per-chunk local h_end
__device__ float g_h0[NCH * DI * NST];   // corrected chunk-start h

__device__ __forceinline__ float softplus_f(float x) {
    return fmaxf(x, 0.f) + log1pf(expf(-fabsf(x)));
}

// ---------------- PTX helpers ----------------
__device__ __forceinline__ uint32_t smem_u32(const void* p) {
    uint32_t a;
    asm("{ .reg .u64 t; cvta.to.shared.u64 t, %1; cvt.u32.u64 %0, t; }" : "=r"(a) : "l"(p));
    return a;
}
__device__ __forceinline__ void cp_async16(uint32_t sm, const void* gm) {
    asm volatile("cp.async.ca.shared.global [%0], [%1], 16;" :: "r"(sm), "l"(gm));
}
__device__ __forceinline__ void cp_async16p(void* sm, const void* gm) {
    cp_async16(smem_u32(sm), gm);
}
__device__ __forceinline__ void cp_commit() { asm volatile("cp.async.commit_group;"); }
template<int N> __device__ __forceinline__ void cp_wait() {
    asm volatile("cp.async.wait_group %0;" :: "n"(N));
}
__device__ __forceinline__ void ldm_x4(uint32_t* r, uint32_t addr) {
    asm volatile("ldmatrix.sync.aligned.m8n8.x4.shared.b16 {%0,%1,%2,%3}, [%4];"
        : "=r"(r[0]), "=r"(r[1]), "=r"(r[2]), "=r"(r[3]) : "r"(addr));
}
__device__ __forceinline__ void mma_bf16(float* d, const uint32_t* a, const uint32_t* b) {
    asm volatile(
        "mma.sync.aligned.m16n8k16.row.col.f32.bf16.bf16.f32 "
        "{%0,%1,%2,%3}, {%4,%5,%6,%7}, {%8,%9}, {%0,%1,%2,%3};"
        : "+f"(d[0]), "+f"(d[1]), "+f"(d[2]), "+f"(d[3])
        : "r"(a[0]), "r"(a[1]), "r"(a[2]), "r"(a[3]), "r"(b[0]), "r"(b[1]));
}

// ============================================================================
// fp32 -> (bf16 hi, bf16 lo) split
// ============================================================================
__global__ __launch_bounds__(256)
void cvt_hilo(const float* __restrict__ src, __nv_bfloat16* __restrict__ hi,
              __nv_bfloat16* __restrict__ lo, int n4)
{
    int i = blockIdx.x * blockDim.x + threadIdx.x;
    if (i >= n4) return;
    float4 v = ((const float4*)src)[i];
    __nv_bfloat16 hx = __float2bfloat16_rn(v.x);
    __nv_bfloat16 hy = __float2bfloat16_rn(v.y);
    __nv_bfloat16 hz = __float2bfloat16_rn(v.z);
    __nv_bfloat16 hw = __float2bfloat16_rn(v.w);
    __nv_bfloat16 lx = __float2bfloat16_rn(v.x - __bfloat162float(hx));
    __nv_bfloat16 ly = __float2bfloat16_rn(v.y - __bfloat162float(hy));
    __nv_bfloat16 lz = __float2bfloat16_rn(v.z - __bfloat162float(hz));
    __nv_bfloat16 lw = __float2bfloat16_rn(v.w - __bfloat162float(hw));
    ((__nv_bfloat162*)hi)[i*2+0] = __nv_bfloat162(hx, hy);
    ((__nv_bfloat162*)hi)[i*2+1] = __nv_bfloat162(hz, hw);
    ((__nv_bfloat162*)lo)[i*2+0] = __nv_bfloat162(lx, ly);
    ((__nv_bfloat162*)lo)[i*2+1] = __nv_bfloat162(lz, lw);
}

// ============================================================================
// bf16x3 emulated-fp32 GEMM via mma.sync m16n8k16.
//   C[M,Nc] = A[M,K] @ W[Nc,K]^T + bias   (both K-contiguous)
// Block 128x128, BK=32, 8 warps (4M x 2N), warp tile 32x64.
// SMEM rows padded to 40 bf16 (80B): rows hit distinct 16B bank groups ->
// conflict-free ldmatrix with no XOR swizzle.
// ACT==1: softplus on output cols < DI.
// ============================================================================
#define ROWEL 40
#define MATB  (128 * ROWEL * 2)      // 10240 bytes per matrix tile
#define BUFB  (4 * MATB)             // Ahi, Alo, Whi, Wlo
#define GEMM_SMEM (2 * BUFB)         // 81920

__device__ __forceinline__ void gemm_load_stage(
    uint32_t sb, int buf, int k0,
    const __nv_bfloat16* __restrict__ Ahi, const __nv_bfloat16* __restrict__ Alo,
    const __nv_bfloat16* __restrict__ Whi, const __nv_bfloat16* __restrict__ Wlo,
    int m0, int n0, int Nc, int Kd, int tid)
{
    uint32_t base = sb + buf * BUFB;
#pragma unroll
    for (int it = 0; it < 8; it++) {
        int q   = tid + it * 256;
        int mat = q >> 9;          // 0:Ahi 1:Alo 2:Whi 3:Wlo
        int rem = q & 511;
        int row = rem >> 2;
        int ch  = rem & 3;
        uint32_t dst = base + mat * MATB + row * (ROWEL * 2) + ch * 16;
        const __nv_bfloat16* src;
        if (mat < 2) {
            const __nv_bfloat16* bp = (mat == 0) ? Ahi : Alo;
            src = bp + (size_t)(m0 + row) * Kd + k0 + ch * 8;
        } else {
            int wr = n0 + row; if (wr >= Nc) wr = Nc - 1;   // clamp; epilogue guards
            const __nv_bfloat16* bp = (mat == 2) ? Whi : Wlo;
            src = bp + (size_t)wr * Kd + k0 + ch * 8;
        }
        cp_async16(dst, src);
    }
    cp_commit();
}

template<int ACT>
__global__ __launch_bounds__(256, 1)
void gemm_mma(const __nv_bfloat16* __restrict__ Ahi, const __nv_bfloat16* __restrict__ Alo,
              const __nv_bfloat16* __restrict__ Whi, const __nv_bfloat16* __restrict__ Wlo,
              const float* __restrict__ bias, float* __restrict__ C,
              int Nc, int Kd, int ldc)
{
    extern __shared__ char smraw[];
    uint32_t sb = smem_u32(smraw);

    int tid  = threadIdx.x;
    int wid  = tid >> 5;
    int lane = tid & 31;
    int wm   = wid & 3;          // warp M index (0..3)
    int wn   = wid >> 2;         // warp N index (0..1)
    int m0 = blockIdx.y * 128;
    int n0 = blockIdx.x * 128;

    float acc[2][8][4];
#pragma unroll
    for (int i = 0; i < 2; i++)
#pragma unroll
        for (int j = 0; j < 8; j++)
#pragma unroll
            for (int k = 0; k < 4; k++) acc[i][j][k] = 0.f;

    // ldmatrix lane addressing (within the tile)
    int aRow = wm * 32 + (lane & 15);
    int aColHalf = (lane >> 4) << 3;               // 0 or 8
    int bRow = wn * 64 + ((lane >> 4) & 1) * 8 + (lane & 7);
    int bColHalf = ((lane >> 3) & 1) << 3;         // 0 or 8

    const int NSTAGE = Kd / 32;
    gemm_load_stage(sb, 0, 0, Ahi, Alo, Whi, Wlo, m0, n0, Nc, Kd, tid);

    for (int s = 0; s < NSTAGE; s++) {
        int buf = s & 1;
        if (s + 1 < NSTAGE) {
            gemm_load_stage(sb, buf ^ 1, (s + 1) * 32, Ahi, Alo, Whi, Wlo, m0, n0, Nc, Kd, tid);
            cp_wait<1>();
        } else {
            cp_wait<0>();
        }
        __syncthreads();

        uint32_t bA = sb + buf * BUFB;
        uint32_t bW = bA + 2 * MATB;
#pragma unroll
        for (int kc = 0; kc < 2; kc++) {
            int acol = kc * 16 + aColHalf;
            int bcol = kc * 16 + bColHalf;
            uint32_t ah[2][4], al[2][4];
#pragma unroll
            for (int mt = 0; mt < 2; mt++) {
                uint32_t off = (uint32_t)((aRow + mt * 16) * (ROWEL * 2) + acol * 2);
                ldm_x4(ah[mt], bA + off);
                ldm_x4(al[mt], bA + MATB + off);
            }
#pragma unroll
            for (int ntp = 0; ntp < 4; ntp++) {
                uint32_t off = (uint32_t)((bRow + ntp * 16) * (ROWEL * 2) + bcol * 2);
                uint32_t bh[4], bl[4];
                ldm_x4(bh, bW + off);
                ldm_x4(bl, bW + MATB + off);
#pragma unroll
                for (int mt = 0; mt < 2; mt++) {
                    mma_bf16(acc[mt][2*ntp+0], ah[mt], bh + 0);
                    mma_bf16(acc[mt][2*ntp+1], ah[mt], bh + 2);
                    mma_bf16(acc[mt][2*ntp+0], ah[mt], bl + 0);
                    mma_bf16(acc[mt][2*ntp+1], ah[mt], bl + 2);
                    mma_bf16(acc[mt][2*ntp+0], al[mt], bh + 0);
                    mma_bf16(acc[mt][2*ntp+1], al[mt], bh + 2);
                }
            }
        }
        __syncthreads();
    }

    // epilogue
#pragma unroll
    for (int mt = 0; mt < 2; mt++) {
        int r0 = m0 + wm * 32 + mt * 16 + (lane >> 2);
#pragma unroll
        for (int nt = 0; nt < 8; nt++) {
            int c = n0 + wn * 64 + nt * 8 + 2 * (lane & 3);
            if (c < Nc) {
                float b0 = bias[c], b1 = bias[c + 1];
                float v0 = acc[mt][nt][0] + b0;
                float v1 = acc[mt][nt][1] + b1;
                float v2 = acc[mt][nt][2] + b0;
                float v3 = acc[mt][nt][3] + b1;
                if (ACT == 1) {
                    if (c     < DI) { v0 = softplus_f(v0); v2 = softplus_f(v2); }
                    if (c + 1 < DI) { v1 = softplus_f(v1); v3 = softplus_f(v3); }
                }
                *(float2*)&C[(size_t)r0 * ldc + c]       = make_float2(v0, v1);
                *(float2*)&C[(size_t)(r0 + 8) * ldc + c] = make_float2(v2, v3);
            }
        }
    }
}

// ============================================================================
// Depthwise causal conv (K=4) + silu
// ============================================================================
__global__ __launch_bounds__(256)
void conv_silu_k(const float* __restrict__ Wc, const float* __restrict__ bc)
{
    int idx = blockIdx.x * blockDim.x + threadIdx.x;
    int t = idx >> 11;
    int d = idx & (DI - 1);

    float acc = bc[d];
#pragma unroll
    for (int k = 0; k < KC; k++) {
        int tt = t - (KC - 1) + k;
        if (tt >= 0)
            acc = fmaf(Wc[d * KC + k], g_xr[(size_t)tt * (2 * DI) + d], acc);
    }
    float s = acc / (1.f + __expf(-acc));
    g_xi[(size_t)t * DI + d] = s;
}

// ============================================================================
// Chunked selective scan.
// Pass 1: per chunk, compute (prod dA, local h_end) per (d,n).
// Pass 2: sequential combine over chunks -> h0 per chunk.
// Pass 3: rescan each chunk from h0; full y + gating epilogue.
// ============================================================================
#define TT 32

// ---- pass 1 ----
__global__ __launch_bounds__(256, 1)
void scan_p1(const float* __restrict__ A_log)
{
    __shared__ float s_delta[2][TT][16];
    __shared__ float s_B    [2][TT][16];
    __shared__ float s_xi   [2][TT][16];

    int tid = threadIdx.x;
    int n  = tid & 15;
    int dl = tid >> 4;
    int dbase = blockIdx.x * 16;
    int d = dbase + dl;
    int chunk = blockIdx.y;
    int tbase = chunk * CH;

    float A_dn = -expf(A_log[d * NST + n]);
    float ap = 1.f, h = 0.f;

    auto issue = [&](int t0, int buf) {
        for (int q = tid; q < 3 * TT * 4; q += 256) {
            int arr = q >> 7;
            int rem = q & 127;
            int tq  = rem >> 2;
            int v   = (rem & 3) * 4;
            int t   = tbase + t0 + tq;
            const float* g; float* s;
            if      (arr == 0) { g = g_proj + (size_t)t * NPROJ + dbase + v; s = &s_delta[buf][tq][v]; }
            else if (arr == 1) { g = g_proj + (size_t)t * NPROJ + DI + v;    s = &s_B[buf][tq][v]; }
            else               { g = g_xi   + (size_t)t * DI + dbase + v;    s = &s_xi[buf][tq][v]; }
            cp_async16p(s, g);
        }
        cp_commit();
    };

    issue(0, 0);
    int buf = 0;
    const int NT = CH / TT;   // 4
    for (int it = 0; it < NT; it++) {
        if (it + 1 < NT) { issue((it + 1) * TT, buf ^ 1); cp_wait<1>(); }
        else             { cp_wait<0>(); }
        __syncthreads();
#pragma unroll 8
        for (int tt = 0; tt < TT; tt++) {
            float del = s_delta[buf][tt][dl];
            float bv  = s_B[buf][tt][n];
            float xv  = s_xi[buf][tt][dl];
            float dA  = __expf(del * A_dn);
            ap *= dA;
            h = fmaf(dA, h, del * bv * xv);
        }
        __syncthreads();
        buf ^= 1;
    }
    int idx = (chunk * DI + d) * NST + n;
    g_cA[idx] = ap;
    g_cB[idx] = h;
}

// ---- pass 2: combine ----
__global__ __launch_bounds__(256)
void scan_comb()
{
    int dn = blockIdx.x * blockDim.x + threadIdx.x;   // (d,n) flat, 32768
    float h = 0.f;
#pragma unroll
    for (int c = 0; c < NCH; c++) {
        int idx = c * (DI * NST) + dn;
        g_h0[idx] = h;
        h = fmaf(g_cA[idx], h, g_cB[idx]);
    }
}

// ---- pass 3 ----
__global__ __launch_bounds__(256, 1)
void scan_p3(const float* __restrict__ A_log, const float* __restrict__ Dv)
{
    __shared__ float s_delta[2][TT][16];
    __shared__ float s_B    [2][TT][16];
    __shared__ float s_C    [2][TT][16];
    __shared__ float s_xi   [2][TT][16];
    __shared__ float s_res  [2][TT][16];

    int tid = threadIdx.x;
    int n  = tid & 15;
    int dl = tid >> 4;
    int dbase = blockIdx.x * 16;
    int d = dbase + dl;
    int chunk = blockIdx.y;
    int tbase = chunk * CH;

    float A_dn = -expf(A_log[d * NST + n]);
    float Dd   = Dv[d];
    float h    = g_h0[(chunk * DI + d) * NST + n];

    auto issue = [&](int t0, int buf) {
        for (int q = tid; q < 5 * TT * 4; q += 256) {
            int arr = q >> 7;
            int rem = q & 127;
            int tq  = rem >> 2;
            int v   = (rem & 3) * 4;
            int t   = tbase + t0 + tq;
            const float* g; float* s;
            if      (arr == 0) { g = g_proj + (size_t)t * NPROJ + dbase + v;       s = &s_delta[buf][tq][v]; }
            else if (arr == 1) { g = g_proj + (size_t)t * NPROJ + DI + v;          s = &s_B[buf][tq][v]; }
            else if (arr == 2) { g = g_proj + (size_t)t * NPROJ + DI + NST + v;    s = &s_C[buf][tq][v]; }
            else if (arr == 3) { g = g_xi   + (size_t)t * DI + dbase + v;          s = &s_xi[buf][tq][v]; }
            else               { g = g_xr   + (size_t)t * (2*DI) + DI + dbase + v; s = &s_res[buf][tq][v]; }
            cp_async16p(s, g);
        }
        cp_commit();
    };

    issue(0, 0);
    int buf = 0;
    const int NT = CH / TT;   // 4
    for (int it = 0; it < NT; it++) {
        if (it + 1 < NT) { issue((it + 1) * TT, buf ^ 1); cp_wait<1>(); }
        else             { cp_wait<0>(); }
        __syncthreads();

        int t0 = tbase + it * TT;
#pragma unroll 8
        for (int tt = 0; tt < TT; tt++) {
            float del = s_delta[buf][tt][dl];
            float bv  = s_B[buf][tt][n];
            float cv  = s_C[buf][tt][n];
            float xv  = s_xi[buf][tt][dl];
            float dA  = __expf(del * A_dn);
            h = fmaf(dA, h, del * bv * xv);
            float yv = h * cv;
            yv += __shfl_xor_sync(0xffffffffu, yv, 1);
            yv += __shfl_xor_sync(0xffffffffu, yv, 2);
            yv += __shfl_xor_sync(0xffffffffu, yv, 4);
            yv += __shfl_xor_sync(0xffffffffu, yv, 8);
            if (n == 0) {
                float r  = s_res[buf][tt][dl];
                float y  = fmaf(xv, Dd, yv);
                float zv = y * (r / (1.f + __expf(-r)));
                g_z[(size_t)(t0 + tt) * DI + d] = zv;
            }
        }
        __syncthreads();
        buf ^= 1;
    }
}

// ============================================================================
// launch
// ============================================================================
extern "C" void kernel_launch(void* const* d_in, const int* in_sizes, int n_in,
                              void* d_out, int out_size)
{
    const float* x      = (const float*)d_in[0];
    const float* W_in   = (const float*)d_in[1];
    const float* b_in   = (const float*)d_in[2];
    const float* W_conv = (const float*)d_in[3];
    const float* b_conv = (const float*)d_in[4];
    const float* W_x    = (const float*)d_in[5];
    const float* b_x    = (const float*)d_in[6];
    const float* W_out  = (const float*)d_in[7];
    const float* b_out  = (const float*)d_in[8];
    const float* A_log  = (const float*)d_in[9];
    const float* Dv     = (const float*)d_in[10];
    float* out = (float*)d_out;

    float *xr, *xi, *proj, *z;
    __nv_bfloat16 *ahi, *alo, *whi, *wlo;
    cudaGetSymbolAddress((void**)&xr,   g_xr);
    cudaGetSymbolAddress((void**)&xi,   g_xi);
    cudaGetSymbolAddress((void**)&proj, g_proj);
    cudaGetSymbolAddress((void**)&z,    g_z);
    cudaGetSymbolAddress((void**)&ahi,  g_ahi);
    cudaGetSymbolAddress((void**)&alo,  g_alo);
    cudaGetSymbolAddress((void**)&whi,  g_whi);
    cudaGetSymbolAddress((void**)&wlo,  g_wlo);

    static bool attr_done = false;
    if (!attr_done) {
        cudaFuncSetAttribute(gemm_mma<0>, cudaFuncAttributeMaxDynamicSharedMemorySize, GEMM_SMEM);
        cudaFuncSetAttribute(gemm_mma<1>, cudaFuncAttributeMaxDynamicSharedMemorySize, GEMM_SMEM);
        attr_done = true;
    }

    // ---- GEMM1: xr = x @ W_in.T + b_in   (M=2048, Nc=4096, K=1024) ----
    {
        int nA = L_SEQ * DM / 4, nW = (2 * DI) * DM / 4;
        cvt_hilo<<<(nA + 255) / 256, 256>>>(x, ahi, alo, nA);
        cvt_hilo<<<(nW + 255) / 256, 256>>>(W_in, whi, wlo, nW);
        dim3 grid((2 * DI) / 128, L_SEQ / 128);
        gemm_mma<0><<<grid, 256, GEMM_SMEM>>>(ahi, alo, whi, wlo, b_in, xr,
                                              2 * DI, DM, 2 * DI);
    }
    // ---- conv + silu ----
    conv_silu_k<<<(L_SEQ * DI) / 256, 256>>>(W_conv, b_conv);

    // ---- GEMM2: proj = xi @ W_x.T + b_x (softplus on delta) (Nc=2080, K=2048) ----
    {
        int nA = L_SEQ * DI / 4, nW = NPROJ * DI / 4;
        cvt_hilo<<<(nA + 255) / 256, 256>>>(xi, ahi, alo, nA);
        cvt_hilo<<<(nW + 255) / 256, 256>>>(W_x, whi, wlo, nW);
        dim3 grid((NPROJ + 127) / 128, L_SEQ / 128);
        gemm_mma<1><<<grid, 256, GEMM_SMEM>>>(ahi, alo, whi, wlo, b_x, proj,
                                              NPROJ, DI, NPROJ);
    }
    // ---- chunked scan ----
    {
        dim3 g1(DI / 16, NCH);
        scan_p1<<<g1, 256>>>(A_log);
        scan_comb<<<(DI * NST) / 256, 256>>>();
        scan_p3<<<g1, 256>>>(A_log, Dv);
    }
    // ---- GEMM3: out = z @ W_out.T + b_out (Nc=1024, K=2048) ----
    {
        int nA = L_SEQ * DI / 4, nW = DM * DI / 4;
        cvt_hilo<<<(nA + 255) / 256, 256>>>(z, ahi, alo, nA);
        cvt_hilo<<<(nW + 255) / 256, 256>>>(W_out, whi, wlo, nW);
        dim3 grid(DM / 128, L_SEQ / 128);
        gemm_mma<0><<<grid, 256, GEMM_SMEM>>>(ahi, alo, whi, wlo, b_out, out,
                                              DM, DI, DM);
    }
}

// round 4
// speedup vs baseline: 3.5111x; 1.1390x over previous
#include <cuda_runtime.h>
#include <cuda_bf16.h>
#include <math.h>
#include <stdint.h>

// ---------------- problem constants ----------------
#define L_SEQ 2048
#define DM    1024
#define DI    2048
#define NST   16
#define KC    4
#define NPROJ (DI + 2*NST)   // 2080

#define NCH   16             // scan chunks
#define CH    128            // steps per chunk
#define TT    16             // smem time tile
#define SD    64             // d-channels per scan block

// ---------------- scratch (device globals) ----------------
__device__ float g_xr  [L_SEQ * 2 * DI];
__device__ float g_xi  [L_SEQ * DI];
__device__ float g_proj[L_SEQ * NPROJ];

__device__ __nv_bfloat16 g_ahi[L_SEQ * DI];
__device__ __nv_bfloat16 g_alo[L_SEQ * DI];
__device__ __nv_bfloat16 g_whi[NPROJ * DI];
__device__ __nv_bfloat16 g_wlo[NPROJ * DI];

__device__ float g_cA[NCH * DI * NST];
__device__ float g_cB[NCH * DI * NST];
__device__ float g_h0[NCH * DI * NST];

__device__ __forceinline__ float softplus_f(float x) {
    return fmaxf(x, 0.f) + log1pf(expf(-fabsf(x)));
}

// ---------------- PTX helpers ----------------
__device__ __forceinline__ uint32_t smem_u32(const void* p) {
    uint32_t a;
    asm("{ .reg .u64 t; cvta.to.shared.u64 t, %1; cvt.u32.u64 %0, t; }" : "=r"(a) : "l"(p));
    return a;
}
__device__ __forceinline__ void cp_async16(uint32_t sm, const void* gm) {
    asm volatile("cp.async.ca.shared.global [%0], [%1], 16;" :: "r"(sm), "l"(gm));
}
__device__ __forceinline__ void cp_async16p(void* sm, const void* gm) {
    cp_async16(smem_u32(sm), gm);
}
__device__ __forceinline__ void cp_commit() { asm volatile("cp.async.commit_group;"); }
template<int N> __device__ __forceinline__ void cp_wait() {
    asm volatile("cp.async.wait_group %0;" :: "n"(N));
}
__device__ __forceinline__ void ldm_x4(uint32_t* r, uint32_t addr) {
    asm volatile("ldmatrix.sync.aligned.m8n8.x4.shared.b16 {%0,%1,%2,%3}, [%4];"
        : "=r"(r[0]), "=r"(r[1]), "=r"(r[2]), "=r"(r[3]) : "r"(addr));
}
__device__ __forceinline__ void mma_bf16(float* d, const uint32_t* a, const uint32_t* b) {
    asm volatile(
        "mma.sync.aligned.m16n8k16.row.col.f32.bf16.bf16.f32 "
        "{%0,%1,%2,%3}, {%4,%5,%6,%7}, {%8,%9}, {%0,%1,%2,%3};"
        : "+f"(d[0]), "+f"(d[1]), "+f"(d[2]), "+f"(d[3])
        : "r"(a[0]), "r"(a[1]), "r"(a[2]), "r"(a[3]), "r"(b[0]), "r"(b[1]));
}

// ============================================================================
// fp32 -> (bf16 hi, bf16 lo) split
// ============================================================================
__global__ __launch_bounds__(256)
void cvt_hilo(const float* __restrict__ src, __nv_bfloat16* __restrict__ hi,
              __nv_bfloat16* __restrict__ lo, int n4)
{
    int i = blockIdx.x * blockDim.x + threadIdx.x;
    if (i >= n4) return;
    float4 v = ((const float4*)src)[i];
    __nv_bfloat16 hx = __float2bfloat16_rn(v.x);
    __nv_bfloat16 hy = __float2bfloat16_rn(v.y);
    __nv_bfloat16 hz = __float2bfloat16_rn(v.z);
    __nv_bfloat16 hw = __float2bfloat16_rn(v.w);
    __nv_bfloat16 lx = __float2bfloat16_rn(v.x - __bfloat162float(hx));
    __nv_bfloat16 ly = __float2bfloat16_rn(v.y - __bfloat162float(hy));
    __nv_bfloat16 lz = __float2bfloat16_rn(v.z - __bfloat162float(hz));
    __nv_bfloat16 lw = __float2bfloat16_rn(v.w - __bfloat162float(hw));
    ((__nv_bfloat162*)hi)[i*2+0] = __nv_bfloat162(hx, hy);
    ((__nv_bfloat162*)hi)[i*2+1] = __nv_bfloat162(hz, hw);
    ((__nv_bfloat162*)lo)[i*2+0] = __nv_bfloat162(lx, ly);
    ((__nv_bfloat162*)lo)[i*2+1] = __nv_bfloat162(lz, lw);
}

// ============================================================================
// bf16x3 emulated-fp32 GEMM via mma.sync m16n8k16. 3-stage cp.async pipeline.
// ============================================================================
#define ROWEL 40
#define MATB  (128 * ROWEL * 2)      // 10240 bytes per matrix tile
#define BUFB  (4 * MATB)             // Ahi, Alo, Whi, Wlo
#define GEMM_SMEM (3 * BUFB)         // 122880

__device__ __forceinline__ void gemm_load_stage(
    uint32_t sb, int buf, int k0,
    const __nv_bfloat16* __restrict__ Ahi, const __nv_bfloat16* __restrict__ Alo,
    const __nv_bfloat16* __restrict__ Whi, const __nv_bfloat16* __restrict__ Wlo,
    int m0, int n0, int Nc, int Kd, int tid)
{
    uint32_t base = sb + buf * BUFB;
#pragma unroll
    for (int it = 0; it < 8; it++) {
        int q   = tid + it * 256;
        int mat = q >> 9;
        int rem = q & 511;
        int row = rem >> 2;
        int ch  = rem & 3;
        uint32_t dst = base + mat * MATB + row * (ROWEL * 2) + ch * 16;
        const __nv_bfloat16* src;
        if (mat < 2) {
            const __nv_bfloat16* bp = (mat == 0) ? Ahi : Alo;
            src = bp + (size_t)(m0 + row) * Kd + k0 + ch * 8;
        } else {
            int wr = n0 + row; if (wr >= Nc) wr = Nc - 1;
            const __nv_bfloat16* bp = (mat == 2) ? Whi : Wlo;
            src = bp + (size_t)wr * Kd + k0 + ch * 8;
        }
        cp_async16(dst, src);
    }
    cp_commit();
}

template<int ACT>
__global__ __launch_bounds__(256, 1)
void gemm_mma(const __nv_bfloat16* __restrict__ Ahi, const __nv_bfloat16* __restrict__ Alo,
              const __nv_bfloat16* __restrict__ Whi, const __nv_bfloat16* __restrict__ Wlo,
              const float* __restrict__ bias, float* __restrict__ C,
              int Nc, int Kd, int ldc)
{
    extern __shared__ char smraw[];
    uint32_t sb = smem_u32(smraw);

    int tid  = threadIdx.x;
    int wid  = tid >> 5;
    int lane = tid & 31;
    int wm   = wid & 3;
    int wn   = wid >> 2;
    int m0 = blockIdx.y * 128;
    int n0 = blockIdx.x * 128;

    float acc[2][8][4];
#pragma unroll
    for (int i = 0; i < 2; i++)
#pragma unroll
        for (int j = 0; j < 8; j++)
#pragma unroll
            for (int k = 0; k < 4; k++) acc[i][j][k] = 0.f;

    int aRow = wm * 32 + (lane & 15);
    int aColHalf = (lane >> 4) << 3;
    int bRow = wn * 64 + ((lane >> 4) & 1) * 8 + (lane & 7);
    int bColHalf = ((lane >> 3) & 1) << 3;

    const int NSTAGE = Kd / 32;
    gemm_load_stage(sb, 0, 0, Ahi, Alo, Whi, Wlo, m0, n0, Nc, Kd, tid);
    gemm_load_stage(sb, 1, 32, Ahi, Alo, Whi, Wlo, m0, n0, Nc, Kd, tid);

    int bufs = 0;
    for (int s = 0; s < NSTAGE; s++) {
        if (s + 2 < NSTAGE) {
            int nb = (bufs + 2) % 3;
            gemm_load_stage(sb, nb, (s + 2) * 32, Ahi, Alo, Whi, Wlo, m0, n0, Nc, Kd, tid);
            cp_wait<2>();
        } else if (s + 1 < NSTAGE) {
            cp_wait<1>();
        } else {
            cp_wait<0>();
        }
        __syncthreads();

        uint32_t bA = sb + bufs * BUFB;
        uint32_t bW = bA + 2 * MATB;
#pragma unroll
        for (int kc = 0; kc < 2; kc++) {
            int acol = kc * 16 + aColHalf;
            int bcol = kc * 16 + bColHalf;
            uint32_t ah[2][4], al[2][4];
#pragma unroll
            for (int mt = 0; mt < 2; mt++) {
                uint32_t off = (uint32_t)((aRow + mt * 16) * (ROWEL * 2) + acol * 2);
                ldm_x4(ah[mt], bA + off);
                ldm_x4(al[mt], bA + MATB + off);
            }
#pragma unroll
            for (int ntp = 0; ntp < 4; ntp++) {
                uint32_t off = (uint32_t)((bRow + ntp * 16) * (ROWEL * 2) + bcol * 2);
                uint32_t bh[4], bl[4];
                ldm_x4(bh, bW + off);
                ldm_x4(bl, bW + MATB + off);
#pragma unroll
                for (int mt = 0; mt < 2; mt++) {
                    mma_bf16(acc[mt][2*ntp+0], ah[mt], bh + 0);
                    mma_bf16(acc[mt][2*ntp+1], ah[mt], bh + 2);
                    mma_bf16(acc[mt][2*ntp+0], ah[mt], bl + 0);
                    mma_bf16(acc[mt][2*ntp+1], ah[mt], bl + 2);
                    mma_bf16(acc[mt][2*ntp+0], al[mt], bh + 0);
                    mma_bf16(acc[mt][2*ntp+1], al[mt], bh + 2);
                }
            }
        }
        __syncthreads();
        bufs = (bufs + 1) % 3;
    }

#pragma unroll
    for (int mt = 0; mt < 2; mt++) {
        int r0 = m0 + wm * 32 + mt * 16 + (lane >> 2);
#pragma unroll
        for (int nt = 0; nt < 8; nt++) {
            int c = n0 + wn * 64 + nt * 8 + 2 * (lane & 3);
            if (c < Nc) {
                float b0 = bias[c], b1 = bias[c + 1];
                float v0 = acc[mt][nt][0] + b0;
                float v1 = acc[mt][nt][1] + b1;
                float v2 = acc[mt][nt][2] + b0;
                float v3 = acc[mt][nt][3] + b1;
                if (ACT == 1) {
                    if (c     < DI) { v0 = softplus_f(v0); v2 = softplus_f(v2); }
                    if (c + 1 < DI) { v1 = softplus_f(v1); v3 = softplus_f(v3); }
                }
                *(float2*)&C[(size_t)r0 * ldc + c]       = make_float2(v0, v1);
                *(float2*)&C[(size_t)(r0 + 8) * ldc + c] = make_float2(v2, v3);
            }
        }
    }
}

// ============================================================================
// Depthwise causal conv (K=4) + silu; writes fp32 xi AND bf16 hi/lo (GEMM2 A)
// ============================================================================
__global__ __launch_bounds__(256)
void conv_silu_k(const float* __restrict__ Wc, const float* __restrict__ bc)
{
    int idx = blockIdx.x * blockDim.x + threadIdx.x;
    int t = idx >> 11;
    int d = idx & (DI - 1);

    float acc = bc[d];
#pragma unroll
    for (int k = 0; k < KC; k++) {
        int tt = t - (KC - 1) + k;
        if (tt >= 0)
            acc = fmaf(Wc[d * KC + k], g_xr[(size_t)tt * (2 * DI) + d], acc);
    }
    float s = acc / (1.f + __expf(-acc));
    size_t o = (size_t)t * DI + d;
    g_xi[o] = s;
    __nv_bfloat16 h = __float2bfloat16_rn(s);
    g_ahi[o] = h;
    g_alo[o] = __float2bfloat16_rn(s - __bfloat162float(h));
}

// ============================================================================
// Chunked selective scan, 4 states per thread.
// Block: 64 d-lanes x 4 n-quads = 256 threads. grid = (DI/64, NCH).
// ============================================================================

// ---- pass 1: per-chunk (prod dA, local h_end) ----
__global__ __launch_bounds__(256, 1)
void scan_p1(const float* __restrict__ A_log)
{
    __shared__ float s_delta[2][TT][SD];
    __shared__ float s_xi   [2][TT][SD];
    __shared__ float s_B    [2][TT][NST];

    int tid = threadIdx.x;
    int nq = tid & 3;
    int dl = tid >> 2;
    int dbase = blockIdx.x * SD;
    int d = dbase + dl;
    int chunk = blockIdx.y;
    int tbase = chunk * CH;

    float4 alv = *(const float4*)&A_log[d * NST + nq * 4];
    float A0 = -__expf(alv.x), A1 = -__expf(alv.y);
    float A2 = -__expf(alv.z), A3 = -__expf(alv.w);

    float ap0 = 1.f, ap1 = 1.f, ap2 = 1.f, ap3 = 1.f;
    float h0 = 0.f, h1 = 0.f, h2 = 0.f, h3 = 0.f;

    auto issue = [&](int t0, int buf) {
        for (int q = tid; q < 576; q += 256) {
            if (q < 512) {
                int arr = q >> 8;           // 0: delta, 1: xi
                int rem = q & 255;
                int tq  = rem >> 4;
                int v   = (rem & 15) * 4;
                int t   = tbase + t0 + tq;
                if (arr == 0)
                    cp_async16p(&s_delta[buf][tq][v], g_proj + (size_t)t * NPROJ + dbase + v);
                else
                    cp_async16p(&s_xi[buf][tq][v], g_xi + (size_t)t * DI + dbase + v);
            } else {
                int rem = q - 512;          // B: 64 tasks
                int tq  = rem >> 2;
                int v   = (rem & 3) * 4;
                int t   = tbase + t0 + tq;
                cp_async16p(&s_B[buf][tq][v], g_proj + (size_t)t * NPROJ + DI + v);
            }
        }
        cp_commit();
    };

    issue(0, 0);
    int buf = 0;
    const int NT = CH / TT;   // 8
    for (int it = 0; it < NT; it++) {
        if (it + 1 < NT) { issue((it + 1) * TT, buf ^ 1); cp_wait<1>(); }
        else             { cp_wait<0>(); }
        __syncthreads();
#pragma unroll
        for (int tt = 0; tt < TT; tt++) {
            float del = s_delta[buf][tt][dl];
            float xv  = s_xi[buf][tt][dl];
            float4 bv = *(const float4*)&s_B[buf][tt][nq * 4];
            float dx = del * xv;
            float e0 = __expf(del * A0), e1 = __expf(del * A1);
            float e2 = __expf(del * A2), e3 = __expf(del * A3);
            ap0 *= e0; ap1 *= e1; ap2 *= e2; ap3 *= e3;
            h0 = fmaf(e0, h0, dx * bv.x);
            h1 = fmaf(e1, h1, dx * bv.y);
            h2 = fmaf(e2, h2, dx * bv.z);
            h3 = fmaf(e3, h3, dx * bv.w);
        }
        __syncthreads();
        buf ^= 1;
    }
    int idx = (chunk * DI + d) * NST + nq * 4;
    *(float4*)&g_cA[idx] = make_float4(ap0, ap1, ap2, ap3);
    *(float4*)&g_cB[idx] = make_float4(h0, h1, h2, h3);
}

// ---- pass 2: sequential combine over chunks ----
__global__ __launch_bounds__(256)
void scan_comb()
{
    int dn = blockIdx.x * blockDim.x + threadIdx.x;
    float h = 0.f;
#pragma unroll
    for (int c = 0; c < NCH; c++) {
        int idx = c * (DI * NST) + dn;
        g_h0[idx] = h;
        h = fmaf(g_cA[idx], h, g_cB[idx]);
    }
}

// ---- pass 3: rescan + gating; writes z directly as bf16 hi/lo (GEMM3 A) ----
__global__ __launch_bounds__(256, 1)
void scan_p3(const float* __restrict__ A_log, const float* __restrict__ Dv)
{
    __shared__ float s_delta[2][TT][SD];
    __shared__ float s_xi   [2][TT][SD];
    __shared__ float s_res  [2][TT][SD];
    __shared__ float s_B    [2][TT][NST];
    __shared__ float s_C    [2][TT][NST];

    int tid = threadIdx.x;
    int nq = tid & 3;
    int dl = tid >> 2;
    int dbase = blockIdx.x * SD;
    int d = dbase + dl;
    int chunk = blockIdx.y;
    int tbase = chunk * CH;

    float4 alv = *(const float4*)&A_log[d * NST + nq * 4];
    float A0 = -__expf(alv.x), A1 = -__expf(alv.y);
    float A2 = -__expf(alv.z), A3 = -__expf(alv.w);
    float Dd = Dv[d];

    float4 hv = *(const float4*)&g_h0[(chunk * DI + d) * NST + nq * 4];
    float h0 = hv.x, h1 = hv.y, h2 = hv.z, h3 = hv.w;

    auto issue = [&](int t0, int buf) {
        for (int q = tid; q < 896; q += 256) {
            if (q < 768) {
                int arr = q >> 8;           // 0: delta, 1: xi, 2: res
                int rem = q & 255;
                int tq  = rem >> 4;
                int v   = (rem & 15) * 4;
                int t   = tbase + t0 + tq;
                if      (arr == 0) cp_async16p(&s_delta[buf][tq][v], g_proj + (size_t)t * NPROJ + dbase + v);
                else if (arr == 1) cp_async16p(&s_xi[buf][tq][v],    g_xi   + (size_t)t * DI + dbase + v);
                else               cp_async16p(&s_res[buf][tq][v],   g_xr   + (size_t)t * (2*DI) + DI + dbase + v);
            } else {
                int rem = q - 768;          // 0..127 : B then C
                int arr = rem >> 6;
                int r2  = rem & 63;
                int tq  = r2 >> 2;
                int v   = (r2 & 3) * 4;
                int t   = tbase + t0 + tq;
                if (arr == 0) cp_async16p(&s_B[buf][tq][v], g_proj + (size_t)t * NPROJ + DI + v);
                else          cp_async16p(&s_C[buf][tq][v], g_proj + (size_t)t * NPROJ + DI + NST + v);
            }
        }
        cp_commit();
    };

    issue(0, 0);
    int buf = 0;
    const int NT = CH / TT;   // 8
    for (int it = 0; it < NT; it++) {
        if (it + 1 < NT) { issue((it + 1) * TT, buf ^ 1); cp_wait<1>(); }
        else             { cp_wait<0>(); }
        __syncthreads();

        int t0 = tbase + it * TT;
#pragma unroll
        for (int tt = 0; tt < TT; tt++) {
            float del = s_delta[buf][tt][dl];
            float xv  = s_xi[buf][tt][dl];
            float4 bv = *(const float4*)&s_B[buf][tt][nq * 4];
            float4 cv = *(const float4*)&s_C[buf][tt][nq * 4];
            float dx = del * xv;
            float e0 = __expf(del * A0), e1 = __expf(del * A1);
            float e2 = __expf(del * A2), e3 = __expf(del * A3);
            h0 = fmaf(e0, h0, dx * bv.x);
            h1 = fmaf(e1, h1, dx * bv.y);
            h2 = fmaf(e2, h2, dx * bv.z);
            h3 = fmaf(e3, h3, dx * bv.w);
            float yv = h0 * cv.x;
            yv = fmaf(h1, cv.y, yv);
            yv = fmaf(h2, cv.z, yv);
            yv = fmaf(h3, cv.w, yv);
            yv += __shfl_xor_sync(0xffffffffu, yv, 1);
            yv += __shfl_xor_sync(0xffffffffu, yv, 2);
            if (nq == 0) {
                float r  = s_res[buf][tt][dl];
                float y  = fmaf(xv, Dd, yv);
                float zv = y * (r / (1.f + __expf(-r)));
                size_t o = (size_t)(t0 + tt) * DI + d;
                __nv_bfloat16 zh = __float2bfloat16_rn(zv);
                g_ahi[o] = zh;
                g_alo[o] = __float2bfloat16_rn(zv - __bfloat162float(zh));
            }
        }
        __syncthreads();
        buf ^= 1;
    }
}

// ============================================================================
// launch
// ============================================================================
extern "C" void kernel_launch(void* const* d_in, const int* in_sizes, int n_in,
                              void* d_out, int out_size)
{
    const float* x      = (const float*)d_in[0];
    const float* W_in   = (const float*)d_in[1];
    const float* b_in   = (const float*)d_in[2];
    const float* W_conv = (const float*)d_in[3];
    const float* b_conv = (const float*)d_in[4];
    const float* W_x    = (const float*)d_in[5];
    const float* b_x    = (const float*)d_in[6];
    const float* W_out  = (const float*)d_in[7];
    const float* b_out  = (const float*)d_in[8];
    const float* A_log  = (const float*)d_in[9];
    const float* Dv     = (const float*)d_in[10];
    float* out = (float*)d_out;

    float *xr, *proj;
    __nv_bfloat16 *ahi, *alo, *whi, *wlo;
    cudaGetSymbolAddress((void**)&xr,   g_xr);
    cudaGetSymbolAddress((void**)&proj, g_proj);
    cudaGetSymbolAddress((void**)&ahi,  g_ahi);
    cudaGetSymbolAddress((void**)&alo,  g_alo);
    cudaGetSymbolAddress((void**)&whi,  g_whi);
    cudaGetSymbolAddress((void**)&wlo,  g_wlo);

    static bool attr_done = false;
    if (!attr_done) {
        cudaFuncSetAttribute(gemm_mma<0>, cudaFuncAttributeMaxDynamicSharedMemorySize, GEMM_SMEM);
        cudaFuncSetAttribute(gemm_mma<1>, cudaFuncAttributeMaxDynamicSharedMemorySize, GEMM_SMEM);
        attr_done = true;
    }

    // ---- GEMM1: xr = x @ W_in.T + b_in   (M=2048, Nc=4096, K=1024) ----
    {
        int nA = L_SEQ * DM / 4, nW = (2 * DI) * DM / 4;
        cvt_hilo<<<(nA + 255) / 256, 256>>>(x, ahi, alo, nA);
        cvt_hilo<<<(nW + 255) / 256, 256>>>(W_in, whi, wlo, nW);
        dim3 grid((2 * DI) / 128, L_SEQ / 128);
        gemm_mma<0><<<grid, 256, GEMM_SMEM>>>(ahi, alo, whi, wlo, b_in, xr,
                                              2 * DI, DM, 2 * DI);
    }
    // ---- conv + silu (also produces GEMM2's bf16 A) ----
    conv_silu_k<<<(L_SEQ * DI) / 256, 256>>>(W_conv, b_conv);

    // ---- GEMM2: proj = xi @ W_x.T + b_x (softplus on delta) ----
    {
        int nW = NPROJ * DI / 4;
        cvt_hilo<<<(nW + 255) / 256, 256>>>(W_x, whi, wlo, nW);
        dim3 grid((NPROJ + 127) / 128, L_SEQ / 128);
        gemm_mma<1><<<grid, 256, GEMM_SMEM>>>(ahi, alo, whi, wlo, b_x, proj,
                                              NPROJ, DI, NPROJ);
    }
    // ---- chunked scan (p3 produces GEMM3's bf16 A) ----
    {
        dim3 g1(DI / SD, NCH);
        scan_p1<<<g1, 256>>>(A_log);
        scan_comb<<<(DI * NST) / 256, 256>>>();
        scan_p3<<<g1, 256>>>(A_log, Dv);
    }
    // ---- GEMM3: out = z @ W_out.T + b_out ----
    {
        int nW = DM * DI / 4;
        cvt_hilo<<<(nW + 255) / 256, 256>>>(W_out, whi, wlo, nW);
        dim3 grid(DM / 128, L_SEQ / 128);
        gemm_mma<0><<<grid, 256, GEMM_SMEM>>>(ahi, alo, whi, wlo, b_out, out,
                                              DM, DI, DM);
    }
}

// round 5
// speedup vs baseline: 4.7592x; 1.3555x over previous
#include <cuda_runtime.h>
#include <cuda_fp16.h>
#include <math.h>
#include <stdint.h>

// ---------------- problem constants ----------------
#define L_SEQ 2048
#define DM    1024
#define DI    2048
#define NST   16
#define KC    4
#define NPROJ (DI + 2*NST)   // 2080

#define NCH   16             // scan chunks
#define CH    128            // steps per chunk
#define TT    16             // smem time tile
#define SD    64             // d-channels per scan block

// ---------------- scratch (device globals) ----------------
__device__ float g_xr  [L_SEQ * 2 * DI];
__device__ float g_xi  [L_SEQ * DI];
__device__ float g_proj[L_SEQ * NPROJ];

__device__ __half g_ahi[L_SEQ * DI];     // activation hi (fp16)
__device__ __half g_alo[L_SEQ * DI];     // activation lo (fp16)
__device__ __half g_wh [NPROJ * DI];     // weight fp16 (single term)

__device__ float g_cA[NCH * DI * NST];
__device__ float g_cB[NCH * DI * NST];
__device__ float g_h0[NCH * DI * NST];

__device__ __forceinline__ float softplus_f(float x) {
    return fmaxf(x, 0.f) + log1pf(expf(-fabsf(x)));
}

// ---------------- PTX helpers ----------------
__device__ __forceinline__ uint32_t smem_u32(const void* p) {
    uint32_t a;
    asm("{ .reg .u64 t; cvta.to.shared.u64 t, %1; cvt.u32.u64 %0, t; }" : "=r"(a) : "l"(p));
    return a;
}
__device__ __forceinline__ void cp_async16(uint32_t sm, const void* gm) {
    asm volatile("cp.async.ca.shared.global [%0], [%1], 16;" :: "r"(sm), "l"(gm));
}
__device__ __forceinline__ void cp_async16p(void* sm, const void* gm) {
    cp_async16(smem_u32(sm), gm);
}
__device__ __forceinline__ void cp_commit() { asm volatile("cp.async.commit_group;"); }
template<int N> __device__ __forceinline__ void cp_wait() {
    asm volatile("cp.async.wait_group %0;" :: "n"(N));
}
__device__ __forceinline__ void ldm_x4(uint32_t* r, uint32_t addr) {
    asm volatile("ldmatrix.sync.aligned.m8n8.x4.shared.b16 {%0,%1,%2,%3}, [%4];"
        : "=r"(r[0]), "=r"(r[1]), "=r"(r[2]), "=r"(r[3]) : "r"(addr));
}
__device__ __forceinline__ void mma_f16(float* d, const uint32_t* a, const uint32_t* b) {
    asm volatile(
        "mma.sync.aligned.m16n8k16.row.col.f32.f16.f16.f32 "
        "{%0,%1,%2,%3}, {%4,%5,%6,%7}, {%8,%9}, {%0,%1,%2,%3};"
        : "+f"(d[0]), "+f"(d[1]), "+f"(d[2]), "+f"(d[3])
        : "r"(a[0]), "r"(a[1]), "r"(a[2]), "r"(a[3]), "r"(b[0]), "r"(b[1]));
}

// ============================================================================
// converts
// ============================================================================
__global__ __launch_bounds__(256)
void cvt_hilo(const float* __restrict__ src, __half* __restrict__ hi,
              __half* __restrict__ lo, int n4)
{
    int i = blockIdx.x * blockDim.x + threadIdx.x;
    if (i >= n4) return;
    float4 v = ((const float4*)src)[i];
    __half hx = __float2half_rn(v.x);
    __half hy = __float2half_rn(v.y);
    __half hz = __float2half_rn(v.z);
    __half hw = __float2half_rn(v.w);
    __half lx = __float2half_rn(v.x - __half2float(hx));
    __half ly = __float2half_rn(v.y - __half2float(hy));
    __half lz = __float2half_rn(v.z - __half2float(hz));
    __half lw = __float2half_rn(v.w - __half2float(hw));
    ((__half2*)hi)[i*2+0] = __half2(hx, hy);
    ((__half2*)hi)[i*2+1] = __half2(hz, hw);
    ((__half2*)lo)[i*2+0] = __half2(lx, ly);
    ((__half2*)lo)[i*2+1] = __half2(lz, lw);
}

__global__ __launch_bounds__(256)
void cvt_h(const float* __restrict__ src, __half* __restrict__ dst, int n4)
{
    int i = blockIdx.x * blockDim.x + threadIdx.x;
    if (i >= n4) return;
    float4 v = ((const float4*)src)[i];
    ((__half2*)dst)[i*2+0] = __half2(__float2half_rn(v.x), __float2half_rn(v.y));
    ((__half2*)dst)[i*2+1] = __half2(__float2half_rn(v.z), __float2half_rn(v.w));
}

// ============================================================================
// fp16 2-term emulated-fp32 GEMM via mma.sync m16n8k16.
//   C = (Ahi + Alo) @ Wh^T + bias    (A exact in fp16 pair, W fp16-quantized)
// Block 128x128, BK=32, 8 warps (4M x 2N). 3-stage cp.async, 2 CTAs/SM.
// ============================================================================
#define ROWEL 40
#define MATB  (128 * ROWEL * 2)      // 10240 bytes per matrix tile
#define BUFB  (3 * MATB)             // Ahi, Alo, Wh
#define GEMM_SMEM (3 * BUFB)         // 92160

__device__ __forceinline__ void gemm_load_stage(
    uint32_t sb, int buf, int k0,
    const __half* __restrict__ Ahi, const __half* __restrict__ Alo,
    const __half* __restrict__ Wh,
    int m0, int n0, int Nc, int Kd, int tid)
{
    uint32_t base = sb + buf * BUFB;
#pragma unroll
    for (int it = 0; it < 6; it++) {
        int q   = tid + it * 256;
        int mat = q >> 9;          // 0:Ahi 1:Alo 2:Wh
        int rem = q & 511;
        int row = rem >> 2;
        int ch  = rem & 3;
        uint32_t dst = base + mat * MATB + row * (ROWEL * 2) + ch * 16;
        const __half* src;
        if (mat < 2) {
            const __half* bp = (mat == 0) ? Ahi : Alo;
            src = bp + (size_t)(m0 + row) * Kd + k0 + ch * 8;
        } else {
            int wr = n0 + row; if (wr >= Nc) wr = Nc - 1;
            src = Wh + (size_t)wr * Kd + k0 + ch * 8;
        }
        cp_async16(dst, src);
    }
    cp_commit();
}

template<int ACT>
__global__ __launch_bounds__(256, 2)
void gemm_mma(const __half* __restrict__ Ahi, const __half* __restrict__ Alo,
              const __half* __restrict__ Wh,
              const float* __restrict__ bias, float* __restrict__ C,
              int Nc, int Kd, int ldc)
{
    extern __shared__ char smraw[];
    uint32_t sb = smem_u32(smraw);

    int tid  = threadIdx.x;
    int wid  = tid >> 5;
    int lane = tid & 31;
    int wm   = wid & 3;
    int wn   = wid >> 2;
    int m0 = blockIdx.y * 128;
    int n0 = blockIdx.x * 128;

    float acc[2][8][4];
#pragma unroll
    for (int i = 0; i < 2; i++)
#pragma unroll
        for (int j = 0; j < 8; j++)
#pragma unroll
            for (int k = 0; k < 4; k++) acc[i][j][k] = 0.f;

    int aRow = wm * 32 + (lane & 15);
    int aColHalf = (lane >> 4) << 3;
    int bRow = wn * 64 + ((lane >> 4) & 1) * 8 + (lane & 7);
    int bColHalf = ((lane >> 3) & 1) << 3;

    const int NSTAGE = Kd / 32;
    gemm_load_stage(sb, 0, 0,  Ahi, Alo, Wh, m0, n0, Nc, Kd, tid);
    gemm_load_stage(sb, 1, 32, Ahi, Alo, Wh, m0, n0, Nc, Kd, tid);

    int bufs = 0;
    for (int s = 0; s < NSTAGE; s++) {
        if (s + 2 < NSTAGE) {
            int nb = (bufs + 2) % 3;
            gemm_load_stage(sb, nb, (s + 2) * 32, Ahi, Alo, Wh, m0, n0, Nc, Kd, tid);
            cp_wait<2>();
        } else if (s + 1 < NSTAGE) {
            cp_wait<1>();
        } else {
            cp_wait<0>();
        }
        __syncthreads();

        uint32_t bA = sb + bufs * BUFB;
        uint32_t bW = bA + 2 * MATB;
#pragma unroll
        for (int kc = 0; kc < 2; kc++) {
            int acol = kc * 16 + aColHalf;
            int bcol = kc * 16 + bColHalf;
            uint32_t ah[2][4], al[2][4];
#pragma unroll
            for (int mt = 0; mt < 2; mt++) {
                uint32_t off = (uint32_t)((aRow + mt * 16) * (ROWEL * 2) + acol * 2);
                ldm_x4(ah[mt], bA + off);
                ldm_x4(al[mt], bA + MATB + off);
            }
#pragma unroll
            for (int ntp = 0; ntp < 4; ntp++) {
                uint32_t off = (uint32_t)((bRow + ntp * 16) * (ROWEL * 2) + bcol * 2);
                uint32_t bh[4];
                ldm_x4(bh, bW + off);
#pragma unroll
                for (int mt = 0; mt < 2; mt++) {
                    mma_f16(acc[mt][2*ntp+0], ah[mt], bh + 0);
                    mma_f16(acc[mt][2*ntp+1], ah[mt], bh + 2);
                    mma_f16(acc[mt][2*ntp+0], al[mt], bh + 0);
                    mma_f16(acc[mt][2*ntp+1], al[mt], bh + 2);
                }
            }
        }
        __syncthreads();
        bufs = (bufs + 1) % 3;
    }

#pragma unroll
    for (int mt = 0; mt < 2; mt++) {
        int r0 = m0 + wm * 32 + mt * 16 + (lane >> 2);
#pragma unroll
        for (int nt = 0; nt < 8; nt++) {
            int c = n0 + wn * 64 + nt * 8 + 2 * (lane & 3);
            if (c < Nc) {
                float b0 = bias[c], b1 = bias[c + 1];
                float v0 = acc[mt][nt][0] + b0;
                float v1 = acc[mt][nt][1] + b1;
                float v2 = acc[mt][nt][2] + b0;
                float v3 = acc[mt][nt][3] + b1;
                if (ACT == 1) {
                    if (c     < DI) { v0 = softplus_f(v0); v2 = softplus_f(v2); }
                    if (c + 1 < DI) { v1 = softplus_f(v1); v3 = softplus_f(v3); }
                }
                *(float2*)&C[(size_t)r0 * ldc + c]       = make_float2(v0, v1);
                *(float2*)&C[(size_t)(r0 + 8) * ldc + c] = make_float2(v2, v3);
            }
        }
    }
}

// ============================================================================
// Depthwise causal conv (K=4) + silu; writes fp32 xi AND fp16 hi/lo (GEMM2 A)
// ============================================================================
__global__ __launch_bounds__(256)
void conv_silu_k(const float* __restrict__ Wc, const float* __restrict__ bc)
{
    int idx = blockIdx.x * blockDim.x + threadIdx.x;
    int t = idx >> 11;
    int d = idx & (DI - 1);

    float acc = bc[d];
#pragma unroll
    for (int k = 0; k < KC; k++) {
        int tt = t - (KC - 1) + k;
        if (tt >= 0)
            acc = fmaf(Wc[d * KC + k], g_xr[(size_t)tt * (2 * DI) + d], acc);
    }
    float s = acc / (1.f + __expf(-acc));
    size_t o = (size_t)t * DI + d;
    g_xi[o] = s;
    __half h = __float2half_rn(s);
    g_ahi[o] = h;
    g_alo[o] = __float2half_rn(s - __half2float(h));
}

// ============================================================================
// Chunked selective scan, 4 states per thread (unchanged from R4).
// ============================================================================
__global__ __launch_bounds__(256, 1)
void scan_p1(const float* __restrict__ A_log)
{
    __shared__ float s_delta[2][TT][SD];
    __shared__ float s_xi   [2][TT][SD];
    __shared__ float s_B    [2][TT][NST];

    int tid = threadIdx.x;
    int nq = tid & 3;
    int dl = tid >> 2;
    int dbase = blockIdx.x * SD;
    int d = dbase + dl;
    int chunk = blockIdx.y;
    int tbase = chunk * CH;

    float4 alv = *(const float4*)&A_log[d * NST + nq * 4];
    float A0 = -__expf(alv.x), A1 = -__expf(alv.y);
    float A2 = -__expf(alv.z), A3 = -__expf(alv.w);

    float ap0 = 1.f, ap1 = 1.f, ap2 = 1.f, ap3 = 1.f;
    float h0 = 0.f, h1 = 0.f, h2 = 0.f, h3 = 0.f;

    auto issue = [&](int t0, int buf) {
        for (int q = tid; q < 576; q += 256) {
            if (q < 512) {
                int arr = q >> 8;
                int rem = q & 255;
                int tq  = rem >> 4;
                int v   = (rem & 15) * 4;
                int t   = tbase + t0 + tq;
                if (arr == 0)
                    cp_async16p(&s_delta[buf][tq][v], g_proj + (size_t)t * NPROJ + dbase + v);
                else
                    cp_async16p(&s_xi[buf][tq][v], g_xi + (size_t)t * DI + dbase + v);
            } else {
                int rem = q - 512;
                int tq  = rem >> 2;
                int v   = (rem & 3) * 4;
                int t   = tbase + t0 + tq;
                cp_async16p(&s_B[buf][tq][v], g_proj + (size_t)t * NPROJ + DI + v);
            }
        }
        cp_commit();
    };

    issue(0, 0);
    int buf = 0;
    const int NT = CH / TT;
    for (int it = 0; it < NT; it++) {
        if (it + 1 < NT) { issue((it + 1) * TT, buf ^ 1); cp_wait<1>(); }
        else             { cp_wait<0>(); }
        __syncthreads();
#pragma unroll
        for (int tt = 0; tt < TT; tt++) {
            float del = s_delta[buf][tt][dl];
            float xv  = s_xi[buf][tt][dl];
            float4 bv = *(const float4*)&s_B[buf][tt][nq * 4];
            float dx = del * xv;
            float e0 = __expf(del * A0), e1 = __expf(del * A1);
            float e2 = __expf(del * A2), e3 = __expf(del * A3);
            ap0 *= e0; ap1 *= e1; ap2 *= e2; ap3 *= e3;
            h0 = fmaf(e0, h0, dx * bv.x);
            h1 = fmaf(e1, h1, dx * bv.y);
            h2 = fmaf(e2, h2, dx * bv.z);
            h3 = fmaf(e3, h3, dx * bv.w);
        }
        __syncthreads();
        buf ^= 1;
    }
    int idx = (chunk * DI + d) * NST + nq * 4;
    *(float4*)&g_cA[idx] = make_float4(ap0, ap1, ap2, ap3);
    *(float4*)&g_cB[idx] = make_float4(h0, h1, h2, h3);
}

__global__ __launch_bounds__(256)
void scan_comb()
{
    int dn = blockIdx.x * blockDim.x + threadIdx.x;
    float h = 0.f;
#pragma unroll
    for (int c = 0; c < NCH; c++) {
        int idx = c * (DI * NST) + dn;
        g_h0[idx] = h;
        h = fmaf(g_cA[idx], h, g_cB[idx]);
    }
}

__global__ __launch_bounds__(256, 1)
void scan_p3(const float* __restrict__ A_log, const float* __restrict__ Dv)
{
    __shared__ float s_delta[2][TT][SD];
    __shared__ float s_xi   [2][TT][SD];
    __shared__ float s_res  [2][TT][SD];
    __shared__ float s_B    [2][TT][NST];
    __shared__ float s_C    [2][TT][NST];

    int tid = threadIdx.x;
    int nq = tid & 3;
    int dl = tid >> 2;
    int dbase = blockIdx.x * SD;
    int d = dbase + dl;
    int chunk = blockIdx.y;
    int tbase = chunk * CH;

    float4 alv = *(const float4*)&A_log[d * NST + nq * 4];
    float A0 = -__expf(alv.x), A1 = -__expf(alv.y);
    float A2 = -__expf(alv.z), A3 = -__expf(alv.w);
    float Dd = Dv[d];

    float4 hv = *(const float4*)&g_h0[(chunk * DI + d) * NST + nq * 4];
    float h0 = hv.x, h1 = hv.y, h2 = hv.z, h3 = hv.w;

    auto issue = [&](int t0, int buf) {
        for (int q = tid; q < 896; q += 256) {
            if (q < 768) {
                int arr = q >> 8;
                int rem = q & 255;
                int tq  = rem >> 4;
                int v   = (rem & 15) * 4;
                int t   = tbase + t0 + tq;
                if      (arr == 0) cp_async16p(&s_delta[buf][tq][v], g_proj + (size_t)t * NPROJ + dbase + v);
                else if (arr == 1) cp_async16p(&s_xi[buf][tq][v],    g_xi   + (size_t)t * DI + dbase + v);
                else               cp_async16p(&s_res[buf][tq][v],   g_xr   + (size_t)t * (2*DI) + DI + dbase + v);
            } else {
                int rem = q - 768;
                int arr = rem >> 6;
                int r2  = rem & 63;
                int tq  = r2 >> 2;
                int v   = (r2 & 3) * 4;
                int t   = tbase + t0 + tq;
                if (arr == 0) cp_async16p(&s_B[buf][tq][v], g_proj + (size_t)t * NPROJ + DI + v);
                else          cp_async16p(&s_C[buf][tq][v], g_proj + (size_t)t * NPROJ + DI + NST + v);
            }
        }
        cp_commit();
    };

    issue(0, 0);
    int buf = 0;
    const int NT = CH / TT;
    for (int it = 0; it < NT; it++) {
        if (it + 1 < NT) { issue((it + 1) * TT, buf ^ 1); cp_wait<1>(); }
        else             { cp_wait<0>(); }
        __syncthreads();

        int t0 = tbase + it * TT;
#pragma unroll
        for (int tt = 0; tt < TT; tt++) {
            float del = s_delta[buf][tt][dl];
            float xv  = s_xi[buf][tt][dl];
            float4 bv = *(const float4*)&s_B[buf][tt][nq * 4];
            float4 cv = *(const float4*)&s_C[buf][tt][nq * 4];
            float dx = del * xv;
            float e0 = __expf(del * A0), e1 = __expf(del * A1);
            float e2 = __expf(del * A2), e3 = __expf(del * A3);
            h0 = fmaf(e0, h0, dx * bv.x);
            h1 = fmaf(e1, h1, dx * bv.y);
            h2 = fmaf(e2, h2, dx * bv.z);
            h3 = fmaf(e3, h3, dx * bv.w);
            float yv = h0 * cv.x;
            yv = fmaf(h1, cv.y, yv);
            yv = fmaf(h2, cv.z, yv);
            yv = fmaf(h3, cv.w, yv);
            yv += __shfl_xor_sync(0xffffffffu, yv, 1);
            yv += __shfl_xor_sync(0xffffffffu, yv, 2);
            if (nq == 0) {
                float r  = s_res[buf][tt][dl];
                float y  = fmaf(xv, Dd, yv);
                float zv = y * (r / (1.f + __expf(-r)));
                size_t o = (size_t)(t0 + tt) * DI + d;
                __half zh = __float2half_rn(zv);
                g_ahi[o] = zh;
                g_alo[o] = __float2half_rn(zv - __half2float(zh));
            }
        }
        __syncthreads();
        buf ^= 1;
    }
}

// ============================================================================
// launch
// ============================================================================
extern "C" void kernel_launch(void* const* d_in, const int* in_sizes, int n_in,
                              void* d_out, int out_size)
{
    const float* x      = (const float*)d_in[0];
    const float* W_in   = (const float*)d_in[1];
    const float* b_in   = (const float*)d_in[2];
    const float* W_conv = (const float*)d_in[3];
    const float* b_conv = (const float*)d_in[4];
    const float* W_x    = (const float*)d_in[5];
    const float* b_x    = (const float*)d_in[6];
    const float* W_out  = (const float*)d_in[7];
    const float* b_out  = (const float*)d_in[8];
    const float* A_log  = (const float*)d_in[9];
    const float* Dv     = (const float*)d_in[10];
    float* out = (float*)d_out;

    float *xr, *proj;
    __half *ahi, *alo, *wh;
    cudaGetSymbolAddress((void**)&xr,   g_xr);
    cudaGetSymbolAddress((void**)&proj, g_proj);
    cudaGetSymbolAddress((void**)&ahi,  g_ahi);
    cudaGetSymbolAddress((void**)&alo,  g_alo);
    cudaGetSymbolAddress((void**)&wh,   g_wh);

    static bool attr_done = false;
    if (!attr_done) {
        cudaFuncSetAttribute(gemm_mma<0>, cudaFuncAttributeMaxDynamicSharedMemorySize, GEMM_SMEM);
        cudaFuncSetAttribute(gemm_mma<1>, cudaFuncAttributeMaxDynamicSharedMemorySize, GEMM_SMEM);
        attr_done = true;
    }

    // ---- GEMM1: xr = x @ W_in.T + b_in   (M=2048, Nc=4096, K=1024) ----
    {
        int nA = L_SEQ * DM / 4, nW = (2 * DI) * DM / 4;
        cvt_hilo<<<(nA + 255) / 256, 256>>>(x, ahi, alo, nA);
        cvt_h<<<(nW + 255) / 256, 256>>>(W_in, wh, nW);
        dim3 grid((2 * DI) / 128, L_SEQ / 128);
        gemm_mma<0><<<grid, 256, GEMM_SMEM>>>(ahi, alo, wh, b_in, xr,
                                              2 * DI, DM, 2 * DI);
    }
    // ---- conv + silu (also produces GEMM2's fp16 A) ----
    conv_silu_k<<<(L_SEQ * DI) / 256, 256>>>(W_conv, b_conv);

    // ---- GEMM2: proj = xi @ W_x.T + b_x (softplus on delta) ----
    {
        int nW = NPROJ * DI / 4;
        cvt_h<<<(nW + 255) / 256, 256>>>(W_x, wh, nW);
        dim3 grid((NPROJ + 127) / 128, L_SEQ / 128);
        gemm_mma<1><<<grid, 256, GEMM_SMEM>>>(ahi, alo, wh, b_x, proj,
                                              NPROJ, DI, NPROJ);
    }
    // ---- chunked scan (p3 produces GEMM3's fp16 A) ----
    {
        dim3 g1(DI / SD, NCH);
        scan_p1<<<g1, 256>>>(A_log);
        scan_comb<<<(DI * NST) / 256, 256>>>();
        scan_p3<<<g1, 256>>>(A_log, Dv);
    }
    // ---- GEMM3: out = z @ W_out.T + b_out ----
    {
        int nW = DM * DI / 4;
        cvt_h<<<(nW + 255) / 256, 256>>>(W_out, wh, nW);
        dim3 grid(DM / 128, L_SEQ / 128);
        gemm_mma<0><<<grid, 256, GEMM_SMEM>>>(ahi, alo, wh, b_out, out,
                                              DM, DI, DM);
    }
}